// round 4
// baseline (speedup 1.0000x reference)
#include <cuda_runtime.h>

// Round 4: split the sLSTM into (1) a parallel fp32 FFMA2 GEMM that precomputes
// the input projection pre = x @ W^T + b into a 1GB __device__ scratch, and
// (2) a slimmed persistent scan kernel whose per-step k-loop is only the
// recurrent 128 rows of R (96 in registers, 32 in smem), with pre[t] streamed
// from gmem one step ahead.

#define BB 256
#define SS 2048
#define II 64
#define HH 128
#define GG 512
#define REG_K 96
#define SMK   32
#define PTS  (SMK * 2 + 4)      // 68 floats per-thread slab (4tid mod 32 banks)
#define NCTA 128
#define ROWS 2
#define NTHR 256

#define SW_FLOATS (NTHR * PTS)
#define SCAN_SMEM_FLOATS (SW_FLOATS + ROWS * HH + ROWS * GG)
#define SCAN_SMEM_BYTES  (SCAN_SMEM_FLOATS * 4)

// GEMM tiling: CTA = 256 M x 64 N, K=64 fully resident.
#define GM_M 256
#define GM_N 64
#define AS_STRIDE 65            // pad: bank = (m + k) mod 32
#define BD_STRIDE 160           // 8 groups * 20 floats (16 dup + 4 pad) -> conflict-free
#define GEMM_SMEM_FLOATS (GM_M * AS_STRIDE + II * BD_STRIDE)
#define GEMM_SMEM_BYTES  (GEMM_SMEM_FLOATS * 4)

typedef unsigned long long u64;

__device__ float g_pre[(long long)BB * SS * GG];   // 1 GB scratch (module-scope)

__device__ __forceinline__ u64 ffma2(u64 a, u64 b, u64 c) {
    u64 d;
    asm("fma.rn.f32x2 %0, %1, %2, %3;" : "=l"(d) : "l"(a), "l"(b), "l"(c));
    return d;
}
__device__ __forceinline__ u64 packf2(float lo, float hi) {
    u64 r;
    asm("mov.b64 %0, {%1, %2};" : "=l"(r) : "f"(lo), "f"(hi));
    return r;
}
__device__ __forceinline__ float2 unpackf2(u64 v) {
    float2 r;
    asm("mov.b64 {%0, %1}, %2;" : "=f"(r.x), "=f"(r.y) : "l"(v));
    return r;
}
__device__ __forceinline__ float fast_tanh(float x) {
    float xc = fminf(fmaxf(x, -12.0f), 12.0f);
    float e  = __expf(2.0f * xc);
    return __fdividef(e - 1.0f, e + 1.0f);
}

// ---------------------------------------------------------------------------
// Kernel 1: pre[m][g] = sum_k x[m][k] * W[g][k] + b[g],  m = b*SS + s.
// ---------------------------------------------------------------------------
__global__ void __launch_bounds__(256, 2)
pre_gemm_kernel(const float* __restrict__ xg, const float* __restrict__ Wm,
                const float* __restrict__ bias, float* __restrict__ pre)
{
    extern __shared__ float sm[];
    float* As = sm;                      // [GM_M][AS_STRIDE]
    float* Bd = sm + GM_M * AS_STRIDE;   // [II][BD_STRIDE], values duplicated in pairs

    const int tid   = threadIdx.x;
    const int mbase = blockIdx.x * GM_M;
    const int nbase = blockIdx.y * GM_N;

    // load x tile (256 rows x 64 k), transposed-padded store
#pragma unroll
    for (int t = 0; t < 16; t++) {
        int idx = tid + t * 256;
        int row = idx >> 4, kq = idx & 15;
        float4 v = *(const float4*)(xg + (long long)(mbase + row) * II + kq * 4);
        float* p = As + row * AS_STRIDE + kq * 4;
        p[0] = v.x; p[1] = v.y; p[2] = v.z; p[3] = v.w;
    }
    // load W tile (64 g x 64 k), store duplicated: Bd[k][grp*20 + win*2 + {0,1}]
#pragma unroll
    for (int t = 0; t < 4; t++) {
        int idx = tid + t * 256;
        int g = idx >> 4, kq = idx & 15;
        float4 v = *(const float4*)(Wm + (long long)(nbase + g) * II + kq * 4);
        int grp = g >> 3, win = g & 7;
        float vv[4] = {v.x, v.y, v.z, v.w};
#pragma unroll
        for (int j = 0; j < 4; j++) {
            float* p = Bd + (4 * kq + j) * BD_STRIDE + grp * 20 + win * 2;
            p[0] = vv[j]; p[1] = vv[j];
        }
    }
    __syncthreads();

    const int tx = tid & 7;        // N group (8 cols)
    const int ty = tid >> 3;       // M group (8 rows)
    const float* aB = As + ty * 8 * AS_STRIDE;
    const float* bB = Bd + tx * 20;

    u64 acc[4][8];
#pragma unroll
    for (int mi = 0; mi < 4; mi++)
#pragma unroll
        for (int n = 0; n < 8; n++) acc[mi][n] = 0;

#pragma unroll 4
    for (int k = 0; k < II; k++) {
        const ulonglong2* bp = (const ulonglong2*)(bB + (long long)k * BD_STRIDE);
        ulonglong2 b01 = bp[0], b23 = bp[1];       // (b0,b0)(b1,b1) (b2,b2)(b3,b3)
        ulonglong2 b45 = bp[2], b67 = bp[3];
        u64 bd[8] = {b01.x, b01.y, b23.x, b23.y, b45.x, b45.y, b67.x, b67.y};

        float a[8];
#pragma unroll
        for (int i = 0; i < 8; i++) a[i] = aB[i * AS_STRIDE + k];
        u64 ap[4];
#pragma unroll
        for (int mi = 0; mi < 4; mi++) ap[mi] = packf2(a[2 * mi], a[2 * mi + 1]);

#pragma unroll
        for (int mi = 0; mi < 4; mi++)
#pragma unroll
            for (int n = 0; n < 8; n++)
                acc[mi][n] = ffma2(ap[mi], bd[n], acc[mi][n]);
    }

    float bl[8];
#pragma unroll
    for (int n = 0; n < 8; n++) bl[n] = bias[nbase + tx * 8 + n];

#pragma unroll
    for (int mi = 0; mi < 4; mi++) {
        float2 c[8];
#pragma unroll
        for (int n = 0; n < 8; n++) c[n] = unpackf2(acc[mi][n]);
        long long r0 = (long long)(mbase + ty * 8 + 2 * mi) * GG + nbase + tx * 8;
        long long r1 = r0 + GG;
        float4 lo0 = {c[0].x + bl[0], c[1].x + bl[1], c[2].x + bl[2], c[3].x + bl[3]};
        float4 hi0 = {c[4].x + bl[4], c[5].x + bl[5], c[6].x + bl[6], c[7].x + bl[7]};
        float4 lo1 = {c[0].y + bl[0], c[1].y + bl[1], c[2].y + bl[2], c[3].y + bl[3]};
        float4 hi1 = {c[4].y + bl[4], c[5].y + bl[5], c[6].y + bl[6], c[7].y + bl[7]};
        *(float4*)(pre + r0)     = lo0;
        *(float4*)(pre + r0 + 4) = hi0;
        *(float4*)(pre + r1)     = lo1;
        *(float4*)(pre + r1 + 4) = hi1;
    }
}

// ---------------------------------------------------------------------------
// Kernel 2: persistent scan. k-loop = 128 recurrent rows of R only.
// ---------------------------------------------------------------------------
__global__ void __launch_bounds__(NTHR, 1)
slstm_scan_kernel(const float* __restrict__ pre, const float* __restrict__ Rm,
                  float* __restrict__ out)
{
    extern __shared__ float smem[];
    float* sW    = smem;                 // [NTHR][PTS]
    float* hx    = smem + SW_FLOATS;     // [ROWS][HH]
    float* gates = hx + ROWS * HH;       // [ROWS][GG]

    const int tid = threadIdx.x;
    const int c0  = tid;
    const int c1  = tid + NTHR;
    const int b0  = blockIdx.x * ROWS;

    // register weights: R rows [0, 96)
    u64 wr0[REG_K / 2], wr1[REG_K / 2];
#pragma unroll
    for (int j = 0; j < REG_K / 2; j++) {
        wr0[j] = packf2(Rm[(2 * j) * GG + c0], Rm[(2 * j + 1) * GG + c0]);
        wr1[j] = packf2(Rm[(2 * j) * GG + c1], Rm[(2 * j + 1) * GG + c1]);
    }
    // smem weights: R rows [96, 128), interleaved per 4-k chunk
    {
        float* slab = sW + tid * PTS;
#pragma unroll
        for (int kc = 0; kc < SMK; kc += 4) {
            int k = REG_K + kc;
            slab[kc * 2 + 0] = Rm[(k + 0) * GG + c0];
            slab[kc * 2 + 1] = Rm[(k + 1) * GG + c0];
            slab[kc * 2 + 2] = Rm[(k + 0) * GG + c1];
            slab[kc * 2 + 3] = Rm[(k + 1) * GG + c1];
            slab[kc * 2 + 4] = Rm[(k + 2) * GG + c0];
            slab[kc * 2 + 5] = Rm[(k + 3) * GG + c0];
            slab[kc * 2 + 6] = Rm[(k + 2) * GG + c1];
            slab[kc * 2 + 7] = Rm[(k + 3) * GG + c1];
        }
    }

    hx[tid] = 0.0f;                      // 256 threads cover [2][128]
    __syncthreads();

    const int erow = tid >> 7;
    const int ehid = tid & 127;

    float c_ = 0.0f, n_ = 0.0f, m_ = 0.0f;

    const float* hx0 = hx;
    const float* hx1 = hx + HH;
    const float* sWg = sW + tid * PTS;

    const float* pr0 = pre + (long long)(b0)     * SS * GG;
    const float* pr1 = pre + (long long)(b0 + 1) * SS * GG;

    // pre for step 0
    float p00 = __ldg(pr0 + c0), p01 = __ldg(pr0 + c1);
    float p10 = __ldg(pr1 + c0), p11 = __ldg(pr1 + c1);

#pragma unroll 1
    for (int step = 0; step < SS; step++) {
        // prefetch pre for step+1
        float q00 = 0.f, q01 = 0.f, q10 = 0.f, q11 = 0.f;
        if (step + 1 < SS) {
            long long off = (long long)(step + 1) * GG;
            q00 = __ldg(pr0 + off + c0);
            q01 = __ldg(pr0 + off + c1);
            q10 = __ldg(pr1 + off + c0);
            q11 = __ldg(pr1 + off + c1);
        }

        u64 a00 = 0, a10 = 0, a01 = 0, a11 = 0;

#pragma unroll
        for (int k = 0; k < REG_K; k += 4) {
            ulonglong2 h0 = *(const ulonglong2*)(hx0 + k);
            ulonglong2 h1 = *(const ulonglong2*)(hx1 + k);
            int j = k / 2;
            a00 = ffma2(h0.x, wr0[j],     a00);
            a10 = ffma2(h0.x, wr1[j],     a10);
            a01 = ffma2(h1.x, wr0[j],     a01);
            a11 = ffma2(h1.x, wr1[j],     a11);
            a00 = ffma2(h0.y, wr0[j + 1], a00);
            a10 = ffma2(h0.y, wr1[j + 1], a10);
            a01 = ffma2(h1.y, wr0[j + 1], a01);
            a11 = ffma2(h1.y, wr1[j + 1], a11);
        }
#pragma unroll
        for (int k = 0; k < SMK; k += 4) {
            ulonglong2 wv0 = *(const ulonglong2*)(sWg + k * 2);
            ulonglong2 wv1 = *(const ulonglong2*)(sWg + k * 2 + 4);
            ulonglong2 h0  = *(const ulonglong2*)(hx0 + REG_K + k);
            ulonglong2 h1  = *(const ulonglong2*)(hx1 + REG_K + k);
            a00 = ffma2(h0.x, wv0.x, a00);
            a10 = ffma2(h0.x, wv0.y, a10);
            a01 = ffma2(h1.x, wv0.x, a01);
            a11 = ffma2(h1.x, wv0.y, a11);
            a00 = ffma2(h0.y, wv1.x, a00);
            a10 = ffma2(h0.y, wv1.y, a10);
            a01 = ffma2(h1.y, wv1.x, a01);
            a11 = ffma2(h1.y, wv1.y, a11);
        }

        float2 f00 = unpackf2(a00), f10 = unpackf2(a10);
        float2 f01 = unpackf2(a01), f11 = unpackf2(a11);
        gates[0 * GG + c0] = f00.x + f00.y + p00;
        gates[0 * GG + c1] = f10.x + f10.y + p01;
        gates[1 * GG + c0] = f01.x + f01.y + p10;
        gates[1 * GG + c1] = f11.x + f11.y + p11;
        __syncthreads();

        {
            const float* gr = gates + erow * GG;
            float iv = gr[ehid];
            float fv = gr[HH + ehid];
            float ov = gr[2 * HH + ehid];
            float zv = gr[3 * HH + ehid];

            float tz = fast_tanh(zv);                       // off critical path
            float so = __fdividef(1.0f, 1.0f + __expf(-ov));
            float lf = fminf(fv, 0.0f) - __logf(1.0f + __expf(-fabsf(fv)));
            float mn = fmaxf(lf + m_, iv);
            float ip = __expf(iv - mn);
            float fp = __expf(lf + m_ - mn);
            c_ = fp * c_ + ip * tz;
            n_ = fp * n_ + ip;
            m_ = mn;
            float hv = so * fast_tanh(__fdividef(c_, n_));

            hx[erow * HH + ehid] = hv;
            out[((long long)(b0 + erow) * SS + step) * HH + ehid] = hv;
        }
        __syncthreads();

        p00 = q00; p01 = q01; p10 = q10; p11 = q11;
    }
}

extern "C" void kernel_launch(void* const* d_in, const int* in_sizes, int n_in,
                              void* d_out, int out_size)
{
    const float* xg = (const float*)d_in[0];
    const float* Wm = (const float*)d_in[1];
    const float* Rm = (const float*)d_in[2];
    const float* bv = (const float*)d_in[3];
    if (n_in >= 3 && in_sizes[1] == HH * GG && in_sizes[2] == GG * II) {
        const float* t = Wm; Wm = Rm; Rm = t;
    }
    float* out = (float*)d_out;

    float* pre = nullptr;
    cudaGetSymbolAddress((void**)&pre, g_pre);

    cudaFuncSetAttribute(pre_gemm_kernel,
                         cudaFuncAttributeMaxDynamicSharedMemorySize, GEMM_SMEM_BYTES);
    cudaFuncSetAttribute(slstm_scan_kernel,
                         cudaFuncAttributeMaxDynamicSharedMemorySize, SCAN_SMEM_BYTES);

    dim3 ggrid((BB * SS) / GM_M, GG / GM_N);   // (2048, 8)
    pre_gemm_kernel<<<ggrid, 256, GEMM_SMEM_BYTES>>>(xg, Wm, bv, pre);
    slstm_scan_kernel<<<NCTA, NTHR, SCAN_SMEM_BYTES>>>(pre, Rm, out);
}